// round 12
// baseline (speedup 1.0000x reference)
#include <cuda_runtime.h>

#define DX 16
#define DU 16
#define DA 32
#define NSEQ 256
#define NSTEP 1024

// Precomputed constants (setup kernel): Q = C^T R^-1 C, CtR = C^T R^-1, W = exp(Wlog)
__device__ float g_Q[DX * DX];
__device__ float g_CtR[DX * DA];
__device__ float g_W[DX];

__global__ void ldm_setup(const float* __restrict__ C,
                          const float* __restrict__ Wlog,
                          const float* __restrict__ Rlog)
{
    int t = threadIdx.x;  // 256 threads
    if (t < DX) g_W[t] = expf(Wlog[t]);
    for (int e = t; e < DX * DA; e += blockDim.x) {
        int i = e / DA, j = e % DA;
        g_CtR[e] = C[j * DX + i] * expf(-Rlog[j]);
    }
    if (t < DX * DX) {
        int i = t / DX, l = t % DX;
        float acc = 0.f;
        for (int j = 0; j < DA; j++)
            acc += C[j * DX + i] * expf(-Rlog[j]) * C[j * DX + l];
        g_Q[t] = acc;
    }
}

__global__ __launch_bounds__(128) void ldm_forward(
    const float* __restrict__ a, const float* __restrict__ u,
    const float* __restrict__ mask,
    const float* __restrict__ A, const float* __restrict__ B,
    const float* __restrict__ C,
    const float* __restrict__ mu0, const float* __restrict__ Lam0,
    float* __restrict__ out)
{
    __shared__ float sA[DX][17];
    __shared__ float sB[DX][17];
    __shared__ float sQ[DX][17];
    __shared__ float sW[DX];
    __shared__ float sCt[DX][DA];       // sCt[k][j] = C[j][k]
    __shared__ float sCtR[DX][DA + 1];  // padded: stride-33 kills bank conflicts
    __shared__ float Lp[DX][17];        // Lambda_pred (carry)
    __shared__ float Lt[DX][17];        // Lambda_t
    __shared__ float Ut[DX][17];        // (Lt * A^T)^T
    __shared__ float Gm[DX][17];        // G = I + Lp*Q
    __shared__ float mu_p[DX], mu_ts[DX], r_s[DA], v_s[DX];

    const int tid = threadIdx.x;
    const int b   = blockIdx.x;
    const int i   = tid >> 3;      // output row   (0..15)
    const int j0  = tid & 7;       // output col A (0..7)
    const int j1  = j0 + 8;        // output col B (8..15)

    // ---- load constants / initial state into smem ----
    for (int e = tid; e < DX * DX; e += 128) {
        int r = e >> 4, c = e & 15;
        sA[r][c] = A[e];
        sB[r][c] = B[e];
        sQ[r][c] = g_Q[e];
        Lp[r][c] = Lam0[e];
    }
    for (int e = tid; e < DX * DA; e += 128) {
        int k = e >> 5, j = e & 31;
        sCt[k][j]  = C[j * DX + k];
        sCtR[k][j] = g_CtR[k * DA + j];
    }
    if (tid < DX) { sW[tid] = g_W[tid]; mu_p[tid] = mu0[tid]; }
    __syncthreads();

    const float* a_b = a    + (size_t)b * NSTEP * DA;
    const float* u_b = u    + (size_t)b * NSTEP * DU;
    const float* m_b = mask + (size_t)b * NSTEP;

    float* o_mp = out;                                        // mu_pred_all  [T,B,16]
    float* o_mt = out + (size_t)NSTEP * NSEQ * DX;            // mu_t_all     [T,B,16]
    float* o_Lp = out + (size_t)2 * NSTEP * NSEQ * DX;        // Lam_pred_all [T,B,16,16]
    float* o_Lt = o_Lp + (size_t)NSTEP * NSEQ * DX * DX;      // Lam_t_all    [T,B,16,16]

    #pragma unroll 1
    for (int t = 0; t < NSTEP; t++) {
        // ---- deferred stores of step t-1's post-update prediction (hides STG latency) ----
        if (t > 0) {
            size_t baseL = ((size_t)(t - 1) * NSEQ + b) * (DX * DX);
            o_Lp[baseL + tid]       = Lp[tid >> 4][tid & 15];
            o_Lp[baseL + 128 + tid] = Lp[8 + (tid >> 4)][tid & 15];
            if (tid < DX)
                o_mp[((size_t)(t - 1) * NSEQ + b) * DX + tid] = mu_p[tid];
        }

        const float m = m_b[t];  // same address for all threads -> uniform

        // ---- P1: G = I + Lp*Q  (2 elements per thread) ----
        {
            float g0 = (i == j0) ? 1.f : 0.f;
            float g1 = (i == j1) ? 1.f : 0.f;
            #pragma unroll
            for (int k = 0; k < DX; k++) {
                float lp = Lp[i][k];
                g0 += lp * sQ[k][j0];
                g1 += lp * sQ[k][j1];
            }
            Gm[i][j0] = g0;
            Gm[i][j1] = g1;
        }
        // r = m*a_t - C*mu_pred  (threads 0..31)
        if (tid < DA) {
            float racc = m * a_b[(size_t)t * DA + tid];
            #pragma unroll
            for (int k = 0; k < DX; k++)
                racc -= sCt[k][tid] * mu_p[k];
            r_s[tid] = racc;
        }
        __syncthreads();  // B1

        // ---- P2: warp0 solves (I + Lp*Q) * Lt = Lp  in registers; warp1 computes v ----
        if (m > 0.5f) {
            if (tid < 32) {
                // lane j<16 owns column j of G; lane j>=16 owns column j-16 of RHS (Lp)
                float col[DX];
                #pragma unroll
                for (int q = 0; q < DX; q++)
                    col[q] = (tid < 16) ? Gm[q][tid] : Lp[q][tid - 16];
                #pragma unroll
                for (int k = 0; k < DX; k++) {
                    float pivot = __shfl_sync(0xffffffffu, col[k], k);  // G[k][k]
                    float pinv  = 1.0f / pivot;
                    float pr    = col[k] * pinv;                        // scaled pivot-row elem
                    #pragma unroll
                    for (int q = 0; q < DX; q++) {
                        float f = __shfl_sync(0xffffffffu, col[q], k);  // G[q][k]
                        col[q] = (q == k) ? pr : col[q] - f * pr;
                    }
                }
                if (tid >= 16) {
                    #pragma unroll
                    for (int q = 0; q < DX; q++)
                        Lt[q][tid - 16] = col[q];
                }
            } else if (tid < 48) {
                // v = (C^T R^-1) * r
                int ii = tid - 32;
                float acc = 0.f;
                #pragma unroll
                for (int j = 0; j < DA; j++)
                    acc += sCtR[ii][j] * r_s[j];
                v_s[ii] = acc;
            }
        } else {
            // mask == 0: no measurement update
            Lt[i][j0] = Lp[i][j0];
            Lt[i][j1] = Lp[i][j1];
            if (tid < DX) v_s[tid] = 0.f;
        }
        __syncthreads();  // B2

        // ---- P3: Ut[l][q] = (Lt * A^T)[q][l]; mu_t; store Lambda_t output ----
        {
            float u0 = 0.f, u1 = 0.f;
            #pragma unroll
            for (int k = 0; k < DX; k++) {
                float lt = Lt[i][k];
                u0 += lt * sA[j0][k];
                u1 += lt * sA[j1][k];
            }
            Ut[j0][i] = u0;
            Ut[j1][i] = u1;
        }
        if (tid < DX) {
            // mu_t = mu_pred + m * Lt * v   (K*r == Lt * C^T R^-1 * r)
            float acc = 0.f;
            #pragma unroll
            for (int j = 0; j < DX; j++)
                acc += Lt[tid][j] * v_s[j];
            mu_ts[tid] = mu_p[tid] + m * acc;
        }
        {
            size_t baseL = ((size_t)t * NSEQ + b) * (DX * DX);
            o_Lt[baseL + tid]       = Lt[tid >> 4][tid & 15];
            o_Lt[baseL + 128 + tid] = Lt[8 + (tid >> 4)][tid & 15];
        }
        __syncthreads();  // B3

        // ---- P4: Lp_new = A*(Lt*A^T) + W ; mu_pred_new = A*mu_t + B*u_t ----
        {
            float p0 = (i == j0) ? sW[i] : 0.f;
            float p1 = (i == j1) ? sW[i] : 0.f;
            #pragma unroll
            for (int k = 0; k < DX; k++) {
                float av = sA[i][k];
                p0 += av * Ut[j0][k];
                p1 += av * Ut[j1][k];
            }
            Lp[i][j0] = p0;
            Lp[i][j1] = p1;
        }
        if (tid < DX) {
            float acc = 0.f;
            #pragma unroll
            for (int k = 0; k < DX; k++)
                acc += sA[tid][k] * mu_ts[k];
            if (t < NSTEP - 1) {  // reference zeroes u at the final step
                #pragma unroll
                for (int k = 0; k < DU; k++)
                    acc += sB[tid][k] * u_b[(size_t)t * DU + k];
            }
            o_mt[((size_t)t * NSEQ + b) * DX + tid] = mu_ts[tid];
            mu_p[tid] = acc;
        }
        __syncthreads();  // B4
    }

    // ---- final deferred stores (t = NSTEP-1) ----
    {
        size_t baseL = ((size_t)(NSTEP - 1) * NSEQ + b) * (DX * DX);
        o_Lp[baseL + tid]       = Lp[tid >> 4][tid & 15];
        o_Lp[baseL + 128 + tid] = Lp[8 + (tid >> 4)][tid & 15];
        if (tid < DX)
            o_mp[((size_t)(NSTEP - 1) * NSEQ + b) * DX + tid] = mu_p[tid];
    }
}

extern "C" void kernel_launch(void* const* d_in, const int* in_sizes, int n_in,
                              void* d_out, int out_size)
{
    const float* a    = (const float*)d_in[0];
    const float* u    = (const float*)d_in[1];
    const float* mask = (const float*)d_in[2];
    const float* A    = (const float*)d_in[3];
    const float* B    = (const float*)d_in[4];
    const float* C    = (const float*)d_in[5];
    const float* mu0  = (const float*)d_in[6];
    const float* L0   = (const float*)d_in[7];
    const float* Wlog = (const float*)d_in[8];
    const float* Rlog = (const float*)d_in[9];
    (void)in_sizes; (void)n_in; (void)out_size;

    ldm_setup<<<1, 256>>>(C, Wlog, Rlog);
    ldm_forward<<<NSEQ, 128>>>(a, u, mask, A, B, C, mu0, L0, (float*)d_out);
}

// round 14
// speedup vs baseline: 4.7397x; 4.7397x over previous
#include <cuda_runtime.h>

#define DX 16
#define DU 16
#define DA 32
#define NSEQ 256
#define NSTEP 1024
#define CONV_TH 1e-6f

// Precomputed constants (setup kernel): Q = C^T R^-1 C, CtR = C^T R^-1, W = exp(Wlog)
__device__ float g_Q[DX * DX];
__device__ float g_CtR[DX * DA];
__device__ float g_W[DX];

__global__ void ldm_setup(const float* __restrict__ C,
                          const float* __restrict__ Wlog,
                          const float* __restrict__ Rlog)
{
    int t = threadIdx.x;  // 256 threads
    if (t < DX) g_W[t] = expf(Wlog[t]);
    for (int e = t; e < DX * DA; e += blockDim.x) {
        int i = e / DA, j = e % DA;
        g_CtR[e] = C[j * DX + i] * expf(-Rlog[j]);
    }
    if (t < DX * DX) {
        int i = t / DX, l = t % DX;
        float acc = 0.f;
        for (int j = 0; j < DA; j++)
            acc += C[j * DX + i] * expf(-Rlog[j]) * C[j * DX + l];
        g_Q[t] = acc;
    }
}

__global__ __launch_bounds__(128) void ldm_forward(
    const float* __restrict__ a, const float* __restrict__ u,
    const float* __restrict__ mask,
    const float* __restrict__ A, const float* __restrict__ B,
    const float* __restrict__ C,
    const float* __restrict__ mu0, const float* __restrict__ Lam0,
    float* __restrict__ out)
{
    __shared__ float sA[DX][17];
    __shared__ float sB[DX][17];
    __shared__ float sQ[DX][17];
    __shared__ float sW[DX];
    __shared__ float sCt[DX][DA];       // sCt[k][j] = C[j][k]
    __shared__ float sCtR[DX][DA + 1];
    __shared__ float Lp[DX][17];        // Lambda_pred (carry)
    __shared__ float Lt[DX][17];        // Lambda_t
    __shared__ float Ut[DX][17];        // (Lt * A^T)^T
    __shared__ float Gm[DX][17];        // G = I + Lp*Q
    __shared__ float mu_p[DX], mu_ts[DX], r_s[DA], v_s[DX];
    // fast-mode constants + staging
    __shared__ float sE[DX][17];        // E = I - F*C
    __shared__ float sF[DX][DA + 1];    // F = Lt * C^T R^-1
    __shared__ __align__(16) float sLpStage[DX * DX];
    __shared__ __align__(16) float sLtStage[DX * DX];
    __shared__ float a_sh[DA], u_sh[DU];

    const int tid = threadIdx.x;
    const int b   = blockIdx.x;
    const int i   = tid >> 3;      // output row   (0..15)
    const int j0  = tid & 7;       // output col A (0..7)
    const int j1  = j0 + 8;        // output col B (8..15)

    for (int e = tid; e < DX * DX; e += 128) {
        int r = e >> 4, c = e & 15;
        sA[r][c] = A[e];
        sB[r][c] = B[e];
        sQ[r][c] = g_Q[e];
        Lp[r][c] = Lam0[e];
    }
    for (int e = tid; e < DX * DA; e += 128) {
        int k = e >> 5, j = e & 31;
        sCt[k][j]  = C[j * DX + k];
        sCtR[k][j] = g_CtR[k * DA + j];
    }
    if (tid < DX) { sW[tid] = g_W[tid]; mu_p[tid] = mu0[tid]; }
    __syncthreads();

    const float* a_b = a    + (size_t)b * NSTEP * DA;
    const float* u_b = u    + (size_t)b * NSTEP * DU;
    const float* m_b = mask + (size_t)b * NSTEP;

    float* o_mp = out;
    float* o_mt = out + (size_t)NSTEP * NSEQ * DX;
    float* o_Lp = out + (size_t)2 * NSTEP * NSEQ * DX;
    float* o_Lt = o_Lp + (size_t)NSTEP * NSEQ * DX * DX;

    int te = NSTEP;          // fast-entry step (sentinel = never)
    int checked = 0, mask_ok = 0;

    #pragma unroll 1
    for (int t = 0; t < NSTEP; t++) {
        // deferred stores of step t-1's prediction
        if (t > 0) {
            size_t baseL = ((size_t)(t - 1) * NSEQ + b) * (DX * DX);
            o_Lp[baseL + tid]       = Lp[tid >> 4][tid & 15];
            o_Lp[baseL + 128 + tid] = Lp[8 + (tid >> 4)][tid & 15];
            if (tid < DX)
                o_mp[((size_t)(t - 1) * NSEQ + b) * DX + tid] = mu_p[tid];
        }

        const float m = m_b[t];

        // P1: G = I + Lp*Q
        {
            float g0 = (i == j0) ? 1.f : 0.f;
            float g1 = (i == j1) ? 1.f : 0.f;
            #pragma unroll
            for (int k = 0; k < DX; k++) {
                float lp = Lp[i][k];
                g0 += lp * sQ[k][j0];
                g1 += lp * sQ[k][j1];
            }
            Gm[i][j0] = g0;
            Gm[i][j1] = g1;
        }
        if (tid < DA) {
            float racc = m * a_b[(size_t)t * DA + tid];
            #pragma unroll
            for (int k = 0; k < DX; k++)
                racc -= sCt[k][tid] * mu_p[k];
            r_s[tid] = racc;
        }
        __syncthreads();  // B1

        // P2: warp0 Gauss-Jordan solve (I + Lp*Q)*Lt = Lp; warp1 v = CtR*r
        if (m > 0.5f) {
            if (tid < 32) {
                float col[DX];
                #pragma unroll
                for (int q = 0; q < DX; q++)
                    col[q] = (tid < 16) ? Gm[q][tid] : Lp[q][tid - 16];
                #pragma unroll
                for (int k = 0; k < DX; k++) {
                    float pivot = __shfl_sync(0xffffffffu, col[k], k);
                    float pinv  = 1.0f / pivot;
                    float pr    = col[k] * pinv;
                    #pragma unroll
                    for (int q = 0; q < DX; q++) {
                        float f = __shfl_sync(0xffffffffu, col[q], k);
                        col[q] = (q == k) ? pr : col[q] - f * pr;
                    }
                }
                if (tid >= 16) {
                    #pragma unroll
                    for (int q = 0; q < DX; q++)
                        Lt[q][tid - 16] = col[q];
                }
            } else if (tid < 48) {
                int ii = tid - 32;
                float acc = 0.f;
                #pragma unroll
                for (int j = 0; j < DA; j++)
                    acc += sCtR[ii][j] * r_s[j];
                v_s[ii] = acc;
            }
        } else {
            Lt[i][j0] = Lp[i][j0];
            Lt[i][j1] = Lp[i][j1];
            if (tid < DX) v_s[tid] = 0.f;
        }
        __syncthreads();  // B2

        // P3: Ut = (Lt*A^T)^T ; mu_t ; store Lambda_t
        {
            float u0 = 0.f, u1 = 0.f;
            #pragma unroll
            for (int k = 0; k < DX; k++) {
                float lt = Lt[i][k];
                u0 += lt * sA[j0][k];
                u1 += lt * sA[j1][k];
            }
            Ut[j0][i] = u0;
            Ut[j1][i] = u1;
        }
        if (tid < DX) {
            float acc = 0.f;
            #pragma unroll
            for (int j = 0; j < DX; j++)
                acc += Lt[tid][j] * v_s[j];
            mu_ts[tid] = mu_p[tid] + m * acc;
        }
        {
            size_t baseL = ((size_t)t * NSEQ + b) * (DX * DX);
            o_Lt[baseL + tid]       = Lt[tid >> 4][tid & 15];
            o_Lt[baseL + 128 + tid] = Lt[8 + (tid >> 4)][tid & 15];
        }
        __syncthreads();  // B3

        // P4: Lp_new = A*(Lt*A^T) + W ; mu_pred_new = A*mu_t + B*u_t
        int localok;
        {
            float p0 = (i == j0) ? sW[i] : 0.f;
            float p1 = (i == j1) ? sW[i] : 0.f;
            #pragma unroll
            for (int k = 0; k < DX; k++) {
                float av = sA[i][k];
                p0 += av * Ut[j0][k];
                p1 += av * Ut[j1][k];
            }
            float old0 = Lp[i][j0], old1 = Lp[i][j1];
            localok = (fabsf(p0 - old0) < CONV_TH) && (fabsf(p1 - old1) < CONV_TH);
            Lp[i][j0] = p0;
            Lp[i][j1] = p1;
        }
        if (tid < DX) {
            float acc = 0.f;
            #pragma unroll
            for (int k = 0; k < DX; k++)
                acc += sA[tid][k] * mu_ts[k];
            if (t < NSTEP - 1) {
                #pragma unroll
                for (int k = 0; k < DU; k++)
                    acc += sB[tid][k] * u_b[(size_t)t * DU + k];
            }
            o_mt[((size_t)t * NSEQ + b) * DX + tid] = mu_ts[tid];
            mu_p[tid] = acc;
        }
        int allconv = __syncthreads_and(localok);  // B4 + convergence vote

        if (allconv && m > 0.5f) {
            if (!checked) {
                checked = 1;
                int okm = 1;
                for (int s = t + 1 + tid; s < NSTEP; s += 128)
                    okm = okm && (m_b[s] > 0.5f);
                mask_ok = __syncthreads_and(okm);
            }
            if (mask_ok) { te = t; break; }
        }
    }

    if (te == NSTEP) {
        // never converged: finish exactly as before
        size_t baseL = ((size_t)(NSTEP - 1) * NSEQ + b) * (DX * DX);
        o_Lp[baseL + tid]       = Lp[tid >> 4][tid & 15];
        o_Lp[baseL + 128 + tid] = Lp[8 + (tid >> 4)][tid & 15];
        if (tid < DX)
            o_mp[((size_t)(NSTEP - 1) * NSEQ + b) * DX + tid] = mu_p[tid];
        return;
    }

    // ==================== FAST MODE (Lambda converged) ====================
    // F = Lt * CtR  (16x32)
    for (int e = tid; e < DX * DA; e += 128) {
        int ii = e >> 5, j = e & 31;
        float acc = 0.f;
        #pragma unroll
        for (int k = 0; k < DX; k++)
            acc += Lt[ii][k] * sCtR[k][j];
        sF[ii][j] = acc;
    }
    __syncthreads();
    // E = I - F*C  (16x16); stage Lambda matrices; pending mu_pred[te] store
    for (int e = tid; e < DX * DX; e += 128) {
        int ii = e >> 4, k = e & 15;
        float acc = (ii == k) ? 1.f : 0.f;
        #pragma unroll
        for (int j = 0; j < DA; j++)
            acc -= sF[ii][j] * sCt[k][j];
        sE[ii][k] = acc;
    }
    for (int e = tid; e < DX * DX; e += 128) {
        sLpStage[e] = Lp[e >> 4][e & 15];
        sLtStage[e] = Lt[e >> 4][e & 15];
    }
    if (tid < DX)
        o_mp[((size_t)te * NSEQ + b) * DX + tid] = mu_p[tid];
    __syncthreads();

    if (tid < 32) {
        // ---- warp 0: serial mean chain, syncwarp only ----
        const int lane = tid, half = lane >> 4, li = lane & 15;
        float Er[8], Ar[8], Br[8], Fr[16];
        #pragma unroll
        for (int k = 0; k < 8; k++) {
            Er[k] = sE[li][half * 8 + k];
            Ar[k] = sA[li][half * 8 + k];
            Br[k] = sB[li][half * 8 + k];
        }
        #pragma unroll
        for (int j = 0; j < 16; j++)
            Fr[j] = sF[li][half * 16 + j];

        const int t0 = te + 1;
        float a_p0 = 0.f, a_p1 = 0.f, u_p0 = 0.f, u_p1 = 0.f;
        if (t0 < NSTEP) {
            a_p0 = a_b[(size_t)t0 * DA + lane];
            if (half == 0) u_p0 = u_b[(size_t)t0 * DU + li];
        }
        if (t0 + 1 < NSTEP) {
            a_p1 = a_b[(size_t)(t0 + 1) * DA + lane];
            if (half == 0) u_p1 = u_b[(size_t)(t0 + 1) * DU + li];
        }

        #pragma unroll 1
        for (int t = t0; t < NSTEP; t++) {
            a_sh[lane] = a_p0;
            if (half == 0) u_sh[li] = u_p0;
            __syncwarp();
            a_p0 = a_p1;
            u_p0 = u_p1;
            if (t + 2 < NSTEP) {
                a_p1 = a_b[(size_t)(t + 2) * DA + lane];
                if (half == 0) u_p1 = u_b[(size_t)(t + 2) * DU + li];
            }
            // mu_t = E*mu_p + F*a  (split across lane-pairs)
            float acc = 0.f;
            #pragma unroll
            for (int k = 0; k < 8; k++)
                acc += Er[k] * mu_p[half * 8 + k];
            #pragma unroll
            for (int j = 0; j < 16; j++)
                acc += Fr[j] * a_sh[half * 16 + j];
            acc += __shfl_xor_sync(0xffffffffu, acc, 16);
            if (half == 0) {
                mu_ts[li] = acc;
                o_mt[((size_t)t * NSEQ + b) * DX + li] = acc;
            }
            __syncwarp();
            // mu_pred' = A*mu_t + B*u  (u skipped at final step)
            float acc2 = 0.f;
            #pragma unroll
            for (int k = 0; k < 8; k++)
                acc2 += Ar[k] * mu_ts[half * 8 + k];
            if (t < NSTEP - 1) {
                #pragma unroll
                for (int k = 0; k < 8; k++)
                    acc2 += Br[k] * u_sh[half * 8 + k];
            }
            acc2 += __shfl_xor_sync(0xffffffffu, acc2, 16);
            if (half == 0) {
                mu_p[li] = acc2;
                o_mp[((size_t)t * NSEQ + b) * DX + li] = acc2;
            }
            __syncwarp();
        }
    } else {
        // ---- warps 1-3: blast constant Lambda outputs (no sync vs warp 0) ----
        const int wtid = tid - 32;  // 0..95
        const float4* sp = (const float4*)sLpStage;
        const float4* st = (const float4*)sLtStage;
        float4* dLp = (float4*)o_Lp;
        float4* dLt = (float4*)o_Lt;
        const int nlp = NSTEP - te;          // o_Lp constant for t in [te, 1023]
        for (int s = wtid; s < nlp * 64; s += 96) {
            int tt = s >> 6, slot = s & 63;
            dLp[((size_t)(te + tt) * NSEQ + b) * 64 + slot] = sp[slot];
        }
        const int nlt = NSTEP - (te + 1);    // o_Lt constant for t in [te+1, 1023]
        for (int s = wtid; s < nlt * 64; s += 96) {
            int tt = s >> 6, slot = s & 63;
            dLt[((size_t)(te + 1 + tt) * NSEQ + b) * 64 + slot] = st[slot];
        }
    }
}

extern "C" void kernel_launch(void* const* d_in, const int* in_sizes, int n_in,
                              void* d_out, int out_size)
{
    const float* a    = (const float*)d_in[0];
    const float* u    = (const float*)d_in[1];
    const float* mask = (const float*)d_in[2];
    const float* A    = (const float*)d_in[3];
    const float* B    = (const float*)d_in[4];
    const float* C    = (const float*)d_in[5];
    const float* mu0  = (const float*)d_in[6];
    const float* L0   = (const float*)d_in[7];
    const float* Wlog = (const float*)d_in[8];
    const float* Rlog = (const float*)d_in[9];
    (void)in_sizes; (void)n_in; (void)out_size;

    ldm_setup<<<1, 256>>>(C, Wlog, Rlog);
    ldm_forward<<<NSEQ, 128>>>(a, u, mask, A, B, C, mu0, L0, (float*)d_out);
}